// round 13
// baseline (speedup 1.0000x reference)
#include <cuda_runtime.h>
#include <cuda_fp16.h>
#include <cstdint>

#define NB_T 200
#define NB_NC 3
#define NGROUP 76800
#define NBOX   153600
#define KE     272                    /* extended K: 256 + 10 used + 6 pad */

// Scratch
__device__ __half g_Hh[(size_t)NBOX * KE];     // extended activations [M,KE]
__device__ __half g_W2h[512 * KE];             // extended W2^T [N,KE]
__device__ float  g_pres[NBOX];

__device__ __forceinline__ uint32_t smem_u32(const void* p){
    return (uint32_t)__cvta_generic_to_shared(p);
}

// Fast erf: Abramowitz-Stegun 7.1.26, |abs err| <= 1.5e-7
__device__ __forceinline__ float fast_erf(float x){
    float ax = fabsf(x);
    float t  = __frcp_rn(fmaf(0.3275911f, ax, 1.0f));
    float p  = fmaf(t, 1.061405429f, -1.453152027f);
    p = fmaf(t, p, 1.421413741f);
    p = fmaf(t, p, -0.284496736f);
    p = fmaf(t, p, 0.254829592f);
    p = p * t;
    float e  = __expf(-ax*ax);
    float r  = fmaf(-p, e, 1.0f);
    return copysignf(r, x);
}
__device__ __forceinline__ float gelu_fast(float x){
    return 0.5f * x * (1.0f + fast_erf(x * 0.70710678118654752440f));
}

#define CP16(dst, src) asm volatile("cp.async.cg.shared.global [%0], [%1], 16;\n" :: "r"(dst), "l"(src))
#define CPCOMMIT()     asm volatile("cp.async.commit_group;\n" ::: "memory")
#define CPWAIT1()      asm volatile("cp.async.wait_group 1;\n" ::: "memory")
#define CPWAIT0()      asm volatile("cp.async.wait_group 0;\n" ::: "memory")

#define MBAR_INIT(addr, cnt) \
    asm volatile("mbarrier.init.shared.b64 [%0], %1;\n" :: "r"(addr), "r"(cnt) : "memory")
#define MBAR_ARRIVE(addr) \
    asm volatile("mbarrier.arrive.shared.b64 _, [%0];\n" :: "r"(addr) : "memory")

__device__ __forceinline__ void mbar_wait(uint32_t mbar, uint32_t parity){
    asm volatile(
        "{\n\t.reg .pred P;\n\t"
        "WL_%=:\n\t"
        "mbarrier.try_wait.parity.acquire.cta.shared::cta.b64 P, [%0], %1, 0x989680;\n\t"
        "@P bra.uni WD_%=;\n\t"
        "bra.uni WL_%=;\n\t"
        "WD_%=:\n\t}"
        :: "r"(mbar), "r"(parity) : "memory");
}

__device__ __forceinline__ void ldsm_x4(uint32_t* r, uint32_t addr){
    asm volatile("ldmatrix.sync.aligned.m8n8.x4.shared.b16 {%0,%1,%2,%3}, [%4];\n"
        : "=r"(r[0]), "=r"(r[1]), "=r"(r[2]), "=r"(r[3]) : "r"(addr));
}
__device__ __forceinline__ void mma_f16(float* d, const uint32_t* a, const uint32_t* b){
    asm volatile(
        "mma.sync.aligned.m16n8k16.row.col.f32.f16.f16.f32 "
        "{%0,%1,%2,%3}, {%4,%5,%6,%7}, {%8,%9}, {%0,%1,%2,%3};\n"
        : "+f"(d[0]), "+f"(d[1]), "+f"(d[2]), "+f"(d[3])
        : "r"(a[0]), "r"(a[1]), "r"(a[2]), "r"(a[3]), "r"(b[0]), "r"(b[1]));
}

// extension column value for a box (cols 256..271; >=266 are zero pad)
__device__ __forceinline__ float ext_val(int col, float cat, float conf,
                                         float cx, float cy, int cam){
    if (col < 259) return ((col - 256) == (int)cat) ? 1.0f : 0.0f;
    if (col < 262) return ((col - 259) == cam) ? 1.0f : 0.0f;
    if (col == 262) return conf;
    if (col == 263) return cx;
    if (col == 264) return cy;
    if (col == 265) return 1.0f;
    return 0.0f;
}

// ---------------------------------------------------------------------------
// k_features: 4800 blocks, warp handles 2 groups. Writes extended H rows.
// Blocks < 512 transpose W2 core; blocks 512..543 fill W2 extension columns.
// ---------------------------------------------------------------------------
__global__ __launch_bounds__(256) void k_features(
    const float* __restrict__ box,
    const float* __restrict__ W1, const float* __restrict__ b1,
    const float* __restrict__ lng, const float* __restrict__ lnb,
    const float* __restrict__ dist_w, const float* __restrict__ dist_b,
    const float* __restrict__ W2,
    const float* __restrict__ b2,
    const float* __restrict__ conf_w, const float* __restrict__ conf_b,
    const float* __restrict__ center_w, const float* __restrict__ center_b,
    const float* __restrict__ cat_table, const float* __restrict__ cam_table,
    float* __restrict__ out)
{
    __shared__ __align__(16) float sW1[2560];
    __shared__ __align__(16) float sb1[256], sg[256], sbb[256];
    __shared__ __align__(16) float sdw[512], sdb[512];
    const int tid  = threadIdx.x;
    const int lane = tid & 31;
    const int warp = tid >> 5;

    if (blockIdx.x < 512){                       // W2 core transpose
        int idx = blockIdx.x * 256 + tid;
        int k = idx >> 9, n = idx & 511;
        g_W2h[(size_t)n * KE + k] = __float2half(W2[idx]);
    } else if (blockIdx.x < 544){                // W2 extension cols 256..271
        int e = (blockIdx.x - 512) * 256 + tid;  // 8192 entries
        int n = e >> 4, c = e & 15;
        int col = 256 + c;
        float v;
        if      (col < 259) v = cat_table[(col - 256)*512 + n];
        else if (col < 262) v = cam_table[(col - 259)*512 + n];
        else if (col == 262) v = conf_w[n];
        else if (col == 263) v = center_w[n];
        else if (col == 264) v = center_w[512 + n];
        else if (col == 265) v = b2[n] + conf_b[n] + center_b[n];
        else v = 0.0f;
        g_W2h[(size_t)n * KE + col] = __float2half(v);
    }

    for (int i = tid; i < 2560; i += 256) sW1[i] = W1[i];
    if (tid < 256){ sb1[tid] = b1[tid]; sg[tid] = lng[tid]; sbb[tid] = lnb[tid]; }
    for (int i = tid; i < 512; i += 256){ sdw[i] = dist_w[i]; sdb[i] = dist_b[i]; }
    __syncthreads();

    const float2* sW1f2 = (const float2*)sW1;
    const float2* sb1f2 = (const float2*)sb1;
    const float2* sgf2  = (const float2*)sg;
    const float2* sbbf2 = (const float2*)sbb;
    const float4* sdw4  = (const float4*)sdw;
    const float4* sdb4  = (const float4*)sdb;

    for (int it = 0; it < 2; it++){
        const int g = blockIdx.x * 16 + warp * 2 + it;
        const int cam = g % 3;

        const float4* bd4 = (const float4*)(box + (size_t)g * 12);
        float4 rA = __ldg(bd4), rB = __ldg(bd4+1), rC = __ldg(bd4+2);

        float c0[4], c1[4];
        c0[0]=rA.x/640.0f; c0[1]=rA.y/400.0f; c0[2]=rA.z/640.0f; c0[3]=rA.w/400.0f;
        c1[0]=rB.z/640.0f; c1[1]=rB.w/400.0f; c1[2]=rC.x/640.0f; c1[3]=rC.y/400.0f;
        float cat0=rB.x, conf0=rB.y, cat1=rC.z, conf1=rC.w;

        float s0 = ((c0[0]+c0[1])+c0[2])+c0[3];
        float s1 = ((c1[0]+c1[1])+c1[2])+c1[3];
        float p0 = (s0 != 0.0f) ? 1.0f : 0.0f;
        float p1 = (s1 != 0.0f) ? 1.0f : 0.0f;
        const bool swp = (cat1 + (1.0f-p1)*1000.0f) < (cat0 + (1.0f-p0)*1000.0f);

        float sc[2][4], scat[2], sconf[2], spres[2];
#pragma unroll
        for (int k = 0; k < 4; k++){
            sc[0][k] = swp ? c1[k] : c0[k];
            sc[1][k] = swp ? c0[k] : c1[k];
        }
        scat[0]=swp?cat1:cat0;   scat[1]=swp?cat0:cat1;
        sconf[0]=swp?conf1:conf0; sconf[1]=swp?conf0:conf1;
        spres[0]=swp?p1:p0;       spres[1]=swp?p0:p1;

        float feat[2][10], cxs[2], cys[2];
#pragma unroll
        for (int s = 0; s < 2; s++){
            float x1=sc[s][0], y1=sc[s][1], x2=sc[s][2], y2=sc[s][3];
            float w=x2-x1, h=y2-y1;
            float cx=(x1+x2)*0.5f, cy=(y1+y2)*0.5f;
            cxs[s]=cx; cys[s]=cy;
            feat[s][0]=x1; feat[s][1]=y1; feat[s][2]=x2; feat[s][3]=y2;
            feat[s][4]=w;  feat[s][5]=h;  feat[s][6]=cx; feat[s][7]=cy;
            feat[s][8]=w*h; feat[s][9]=w/(h+1e-6f);
        }

        float2 va[4], vb[4];
#pragma unroll
        for (int q = 0; q < 4; q++){
            int ci = lane + 32*q;
            float2 bias = sb1f2[ci];
            float2 a0 = bias, a1 = bias;
#pragma unroll
            for (int f = 0; f < 10; f++){
                float2 w2 = sW1f2[f*128 + ci];
                a0.x = fmaf(feat[0][f], w2.x, a0.x);
                a0.y = fmaf(feat[0][f], w2.y, a0.y);
                a1.x = fmaf(feat[1][f], w2.x, a1.x);
                a1.y = fmaf(feat[1][f], w2.y, a1.y);
            }
            va[q] = a0; vb[q] = a1;
        }

        float su0 = 0.f, su1 = 0.f;
#pragma unroll
        for (int q = 0; q < 4; q++){ su0 += va[q].x + va[q].y; su1 += vb[q].x + vb[q].y; }
#pragma unroll
        for (int o = 16; o; o >>= 1){
            su0 += __shfl_xor_sync(0xffffffffu, su0, o);
            su1 += __shfl_xor_sync(0xffffffffu, su1, o);
        }
        float mu0 = su0 * (1.0f/256.0f), mu1 = su1 * (1.0f/256.0f);

        float vr0 = 0.f, vr1 = 0.f;
#pragma unroll
        for (int q = 0; q < 4; q++){
            va[q].x -= mu0; va[q].y -= mu0;
            vb[q].x -= mu1; vb[q].y -= mu1;
            vr0 = fmaf(va[q].x, va[q].x, vr0); vr0 = fmaf(va[q].y, va[q].y, vr0);
            vr1 = fmaf(vb[q].x, vb[q].x, vr1); vr1 = fmaf(vb[q].y, vb[q].y, vr1);
        }
#pragma unroll
        for (int o = 16; o; o >>= 1){
            vr0 += __shfl_xor_sync(0xffffffffu, vr0, o);
            vr1 += __shfl_xor_sync(0xffffffffu, vr1, o);
        }
        float rs0 = rsqrtf(vr0 * (1.0f/256.0f) + 1e-5f);
        float rs1 = rsqrtf(vr1 * (1.0f/256.0f) + 1e-5f);

        __half2* hrow0 = (__half2*)(g_Hh + (size_t)(2*g + 0)*KE);
        __half2* hrow1 = (__half2*)(g_Hh + (size_t)(2*g + 1)*KE);
#pragma unroll
        for (int q = 0; q < 4; q++){
            int ci = lane + 32*q;
            float2 gb = sgf2[ci], bv = sbbf2[ci];
            float y00 = gelu_fast(va[q].x * rs0 * gb.x + bv.x);
            float y01 = gelu_fast(va[q].y * rs0 * gb.y + bv.y);
            float y10 = gelu_fast(vb[q].x * rs1 * gb.x + bv.x);
            float y11 = gelu_fast(vb[q].y * rs1 * gb.y + bv.y);
            hrow0[ci] = __floats2half2_rn(y00, y01);
            hrow1[ci] = __floats2half2_rn(y10, y11);
        }
        // extension columns 256..271 (8 half2 per row)
        if (lane < 8){
            int col = 256 + 2*lane;
            hrow0[128 + lane] = __floats2half2_rn(
                ext_val(col,   scat[0], sconf[0], cxs[0], cys[0], cam),
                ext_val(col+1, scat[0], sconf[0], cxs[0], cys[0], cam));
            hrow1[128 + lane] = __floats2half2_rn(
                ext_val(col,   scat[1], sconf[1], cxs[1], cys[1], cam),
                ext_val(col+1, scat[1], sconf[1], cxs[1], cys[1], cam));
        }

        float dx = cxs[0]-cxs[1], dy = cys[0]-cys[1];
        float dist = sqrtf(dx*dx + dy*dy);
        const int bI = g / (NB_T*NB_NC);
        const int rem = g % (NB_T*NB_NC);
        float4* orow4 = (float4*)(out + ((size_t)bI * 1800 + rem) * 512);
#pragma unroll
        for (int jj = 0; jj < 4; jj++){
            int ci = lane + 32*jj;
            float4 w4 = sdw4[ci], b4 = sdb4[ci];
            float4 r4;
            r4.x = fmaf(dist, w4.x, b4.x);
            r4.y = fmaf(dist, w4.y, b4.y);
            r4.z = fmaf(dist, w4.z, b4.z);
            r4.w = fmaf(dist, w4.w, b4.w);
            orow4[ci] = r4;
        }
        if (lane < 2){
            g_pres[2*g + lane] = spres[lane];
        }
    }
}

// ---------------------------------------------------------------------------
// k_gemm: warp-specialized fp16 GEMM over K=272 (8 chunks of 32 + 1 of 16).
// CTA tile 128x128, 8 consumer warps (64x32) + 1 producer. 5-stage mbarrier
// ring. Epilogue = acc*scale + presence mask only. 2 CTAs/SM.
// ---------------------------------------------------------------------------
#define RST 40                              /* stage row stride in halves */
#define STG_BYTES (256*RST*2)               /* 20480 B */
#define NSTG 5
#define NKC  9                              /* 8 full + 1 half chunk */

__global__ __launch_bounds__(288, 2) void k_gemm(
    const float* __restrict__ missing,
    const float* __restrict__ scalep,
    float* __restrict__ out)
{
    extern __shared__ __align__(16) char smraw[];   // 5 stages x 20480 B
    __shared__ __align__(8) uint64_t s_bar[2*NSTG]; // full[0..4], empty[5..9]
    __shared__ float s_pres[128];

    const int tid  = threadIdx.x;
    const int lane = tid & 31;
    const int warp = tid >> 5;

    const int n0 = blockIdx.x * 128;
    const int m0 = blockIdx.y * 128;

    if (tid == 0){
#pragma unroll
        for (int s = 0; s < NSTG; s++){
            MBAR_INIT(smem_u32(&s_bar[s]), 1);          // full: producer arrives
            MBAR_INIT(smem_u32(&s_bar[NSTG+s]), 8);     // empty: 8 consumer warps
        }
    }
    if (tid < 128) s_pres[tid] = g_pres[m0 + tid];
    __syncthreads();

    const uint32_t base = smem_u32(smraw);

    if (warp == 8){
        // ================= producer =================
        int pst = 0, pph = 1;      // empty-wait cursor (starts phase 1)
        int fst = 0;               // full-arrive cursor (lags by 1 chunk)
#pragma unroll 1
        for (int kc = 0; kc < NKC; kc++){
            mbar_wait(smem_u32(&s_bar[NSTG + pst]), pph);
            uint32_t stg = base + pst * STG_BYTES;
            const int ko = kc * 32;
            if (kc < 8){
#pragma unroll
                for (int u = 0; u < 16; u++){           // A: 512 chunks
                    int c = lane + u*32;
                    int row = c >> 2, seg = c & 3;
                    const __half* src = g_Hh + (size_t)(m0 + row) * KE + ko + seg*8;
                    CP16(stg + row*80 + seg*16, src);
                }
#pragma unroll
                for (int u = 0; u < 16; u++){           // B: 512 chunks
                    int c = lane + u*32;
                    int n = c >> 2, seg = c & 3;
                    const __half* src = g_W2h + (size_t)(n0 + n) * KE + ko + seg*8;
                    CP16(stg + (128 + n)*80 + seg*16, src);
                }
            } else {
#pragma unroll
                for (int u = 0; u < 8; u++){            // A: 256 chunks (16 cols)
                    int c = lane + u*32;
                    int row = c >> 1, seg = c & 1;
                    const __half* src = g_Hh + (size_t)(m0 + row) * KE + 256 + seg*8;
                    CP16(stg + row*80 + seg*16, src);
                }
#pragma unroll
                for (int u = 0; u < 8; u++){            // B: 256 chunks
                    int c = lane + u*32;
                    int n = c >> 1, seg = c & 1;
                    const __half* src = g_W2h + (size_t)(n0 + n) * KE + 256 + seg*8;
                    CP16(stg + (128 + n)*80 + seg*16, src);
                }
            }
            CPCOMMIT();
            if (kc >= 1){
                CPWAIT1();
                if (lane == 0) MBAR_ARRIVE(smem_u32(&s_bar[fst]));
                if (++fst == NSTG) fst = 0;
            }
            if (++pst == NSTG){ pst = 0; pph ^= 1; }
        }
        CPWAIT0();
        if (lane == 0) MBAR_ARRIVE(smem_u32(&s_bar[fst]));
    } else {
        // ================= consumers =================
        const int wm  = warp & 1;      // 2 warps along M (64 rows each)
        const int wn  = warp >> 1;     // 4 warps along N (32 cols each)
        const int gid = lane >> 2;
        const int tig = lane & 3;

        const int a_row_sel = (lane & 7) + ((lane >> 3) & 1) * 8;
        const int a_col_sel = ((lane >> 4) & 1) * 8;
        const int b_row_sel = (lane & 7) + ((lane >> 4) & 1) * 8;
        const int b_col_sel = ((lane >> 3) & 1) * 8;

        // preload missing values for this thread's 8 output columns
        float2 ms[4];
#pragma unroll
        for (int ni = 0; ni < 4; ni++){
            int dl = wn*32 + ni*8 + tig*2;
            ms[ni] = *reinterpret_cast<const float2*>(missing + n0 + dl);
        }
        const float scaleV = *scalep;

        float acc[4][4][4];
#pragma unroll
        for (int i = 0; i < 4; i++)
#pragma unroll
            for (int j = 0; j < 4; j++)
#pragma unroll
                for (int k = 0; k < 4; k++) acc[i][j][k] = 0.0f;

        int cst = 0, cph = 0;
#pragma unroll 1
        for (int kc = 0; kc < NKC; kc++){
            mbar_wait(smem_u32(&s_bar[cst]), cph);
            const uint32_t s32 = base + cst * STG_BYTES;
            const int nks = (kc < 8) ? 2 : 1;
#pragma unroll
            for (int ks = 0; ks < 2; ks++){
                if (ks >= nks) break;
                const int kk = ks * 16;
                uint32_t af[4][4];
#pragma unroll
                for (int mi = 0; mi < 4; mi++){
                    int row = wm*64 + mi*16 + a_row_sel;
                    ldsm_x4(af[mi], s32 + (row*RST + kk + a_col_sel)*2);
                }
                uint32_t bf[4][2];
#pragma unroll
                for (int nio = 0; nio < 2; nio++){
                    uint32_t r[4];
                    int nrow = 128 + wn*32 + nio*16 + b_row_sel;
                    ldsm_x4(r, s32 + (nrow*RST + kk + b_col_sel)*2);
                    bf[nio*2  ][0] = r[0]; bf[nio*2  ][1] = r[1];
                    bf[nio*2+1][0] = r[2]; bf[nio*2+1][1] = r[3];
                }
#pragma unroll
                for (int mi = 0; mi < 4; mi++)
#pragma unroll
                    for (int ni = 0; ni < 4; ni++)
                        mma_f16(acc[mi][ni], af[mi], bf[ni]);
            }
            if (lane == 0) MBAR_ARRIVE(smem_u32(&s_bar[NSTG + cst]));
            if (++cst == NSTG){ cst = 0; cph ^= 1; }
        }

        // ---- epilogue: scale + presence mask ----
#pragma unroll
        for (int mi = 0; mi < 4; mi++){
#pragma unroll
            for (int h = 0; h < 2; h++){
                int lm = wm*64 + mi*16 + gid + h*8;
                int m  = m0 + lm;
                float pres = s_pres[lm];
                int bI  = m / 1200;
                int rem = m % 1200;
                float* orow = out + ((size_t)bI*1800 + 600 + rem) * 512 + n0;
#pragma unroll
                for (int ni = 0; ni < 4; ni++){
                    int dl = wn*32 + ni*8 + tig*2;
                    float v0 = acc[mi][ni][h*2 + 0] * scaleV;
                    float v1 = acc[mi][ni][h*2 + 1] * scaleV;
                    if (pres == 0.0f){ v0 = ms[ni].x; v1 = ms[ni].y; }
                    float2 w2; w2.x = v0; w2.y = v1;
                    *reinterpret_cast<float2*>(orow + dl) = w2;
                }
            }
        }
    }
}

// ---------------------------------------------------------------------------
extern "C" void kernel_launch(void* const* d_in, const int* in_sizes, int n_in,
                              void* d_out, int out_size)
{
    const float* box        = (const float*)d_in[0];
    const float* cat_table  = (const float*)d_in[1];
    const float* W1         = (const float*)d_in[2];
    const float* b1         = (const float*)d_in[3];
    const float* lng        = (const float*)d_in[4];
    const float* lnb        = (const float*)d_in[5];
    const float* W2         = (const float*)d_in[6];
    const float* b2         = (const float*)d_in[7];
    const float* conf_w     = (const float*)d_in[8];
    const float* conf_b     = (const float*)d_in[9];
    const float* center_w   = (const float*)d_in[10];
    const float* center_b   = (const float*)d_in[11];
    const float* missing    = (const float*)d_in[12];
    const float* dist_w     = (const float*)d_in[13];
    const float* dist_b     = (const float*)d_in[14];
    const float* cam_table  = (const float*)d_in[15];
    const float* scalep     = (const float*)d_in[16];
    float* out = (float*)d_out;

    const int dyn_smem = NSTG * STG_BYTES;   // 102400 B
    cudaFuncSetAttribute(k_gemm, cudaFuncAttributeMaxDynamicSharedMemorySize, dyn_smem);

    k_features<<<4800, 256>>>(box, W1, b1, lng, lnb, dist_w, dist_b, W2,
                              b2, conf_w, conf_b, center_w, center_b,
                              cat_table, cam_table, out);
    k_gemm<<<dim3(4, 1200), 288, dyn_smem>>>(missing, scalep, out);
}

// round 14
// speedup vs baseline: 1.0203x; 1.0203x over previous
#include <cuda_runtime.h>
#include <cuda_fp16.h>
#include <cstdint>

#define NB_T 200
#define NB_NC 3
#define NGROUP 76800
#define NBOX   153600
#define KE     288                    /* extended K: 256 + 10 used + 22 pad */

// Scratch
__device__ __half g_Hh[(size_t)NBOX * KE];     // extended activations [M,KE]
__device__ __half g_W2h[512 * KE];             // extended W2^T [N,KE]
__device__ float  g_pres[NBOX];

__device__ __forceinline__ uint32_t smem_u32(const void* p){
    return (uint32_t)__cvta_generic_to_shared(p);
}

// Fast erf: Abramowitz-Stegun 7.1.26, |abs err| <= 1.5e-7
__device__ __forceinline__ float fast_erf(float x){
    float ax = fabsf(x);
    float t  = __frcp_rn(fmaf(0.3275911f, ax, 1.0f));
    float p  = fmaf(t, 1.061405429f, -1.453152027f);
    p = fmaf(t, p, 1.421413741f);
    p = fmaf(t, p, -0.284496736f);
    p = fmaf(t, p, 0.254829592f);
    p = p * t;
    float e  = __expf(-ax*ax);
    float r  = fmaf(-p, e, 1.0f);
    return copysignf(r, x);
}
__device__ __forceinline__ float gelu_fast(float x){
    return 0.5f * x * (1.0f + fast_erf(x * 0.70710678118654752440f));
}

#define CP16(dst, src) asm volatile("cp.async.cg.shared.global [%0], [%1], 16;\n" :: "r"(dst), "l"(src))
#define CPCOMMIT()     asm volatile("cp.async.commit_group;\n" ::: "memory")
#define CPWAIT2()      asm volatile("cp.async.wait_group 2;\n" ::: "memory")
#define CPWAIT1()      asm volatile("cp.async.wait_group 1;\n" ::: "memory")
#define CPWAIT0()      asm volatile("cp.async.wait_group 0;\n" ::: "memory")

#define MBAR_INIT(addr, cnt) \
    asm volatile("mbarrier.init.shared.b64 [%0], %1;\n" :: "r"(addr), "r"(cnt) : "memory")
#define MBAR_ARRIVE(addr) \
    asm volatile("mbarrier.arrive.shared.b64 _, [%0];\n" :: "r"(addr) : "memory")

__device__ __forceinline__ void mbar_wait(uint32_t mbar, uint32_t parity){
    asm volatile(
        "{\n\t.reg .pred P;\n\t"
        "WL_%=:\n\t"
        "mbarrier.try_wait.parity.acquire.cta.shared::cta.b64 P, [%0], %1, 0x989680;\n\t"
        "@P bra.uni WD_%=;\n\t"
        "bra.uni WL_%=;\n\t"
        "WD_%=:\n\t}"
        :: "r"(mbar), "r"(parity) : "memory");
}

__device__ __forceinline__ void ldsm_x4(uint32_t* r, uint32_t addr){
    asm volatile("ldmatrix.sync.aligned.m8n8.x4.shared.b16 {%0,%1,%2,%3}, [%4];\n"
        : "=r"(r[0]), "=r"(r[1]), "=r"(r[2]), "=r"(r[3]) : "r"(addr));
}
__device__ __forceinline__ void mma_f16(float* d, const uint32_t* a, const uint32_t* b){
    asm volatile(
        "mma.sync.aligned.m16n8k16.row.col.f32.f16.f16.f32 "
        "{%0,%1,%2,%3}, {%4,%5,%6,%7}, {%8,%9}, {%0,%1,%2,%3};\n"
        : "+f"(d[0]), "+f"(d[1]), "+f"(d[2]), "+f"(d[3])
        : "r"(a[0]), "r"(a[1]), "r"(a[2]), "r"(a[3]), "r"(b[0]), "r"(b[1]));
}

// extension column value for a box
__device__ __forceinline__ float ext_val(int col, float cat, float conf,
                                         float cx, float cy, int cam){
    if (col < 259) return ((col - 256) == (int)cat) ? 1.0f : 0.0f;
    if (col < 262) return ((col - 259) == cam) ? 1.0f : 0.0f;
    if (col == 262) return conf;
    if (col == 263) return cx;
    if (col == 264) return cy;
    if (col == 265) return 1.0f;
    return 0.0f;
}

// ---------------------------------------------------------------------------
// k_features: 4800 blocks, warp handles 2 groups. Writes extended H rows.
// Blocks < 512 transpose W2 core; blocks 512..575 fill W2 extension columns.
// ---------------------------------------------------------------------------
__global__ __launch_bounds__(256) void k_features(
    const float* __restrict__ box,
    const float* __restrict__ W1, const float* __restrict__ b1,
    const float* __restrict__ lng, const float* __restrict__ lnb,
    const float* __restrict__ dist_w, const float* __restrict__ dist_b,
    const float* __restrict__ W2,
    const float* __restrict__ b2,
    const float* __restrict__ conf_w, const float* __restrict__ conf_b,
    const float* __restrict__ center_w, const float* __restrict__ center_b,
    const float* __restrict__ cat_table, const float* __restrict__ cam_table,
    float* __restrict__ out)
{
    __shared__ __align__(16) float sW1[2560];
    __shared__ __align__(16) float sb1[256], sg[256], sbb[256];
    __shared__ __align__(16) float sdw[512], sdb[512];
    const int tid  = threadIdx.x;
    const int lane = tid & 31;
    const int warp = tid >> 5;

    if (blockIdx.x < 512){                       // W2 core transpose
        int idx = blockIdx.x * 256 + tid;
        int k = idx >> 9, n = idx & 511;
        g_W2h[(size_t)n * KE + k] = __float2half(W2[idx]);
    } else if (blockIdx.x < 576){                // W2 extension columns
        int e = (blockIdx.x - 512) * 256 + tid;  // 16384 entries
        int n = e >> 5, c = e & 31;
        int col = 256 + c;
        float v;
        if      (col < 259) v = cat_table[(col - 256)*512 + n];
        else if (col < 262) v = cam_table[(col - 259)*512 + n];
        else if (col == 262) v = conf_w[n];
        else if (col == 263) v = center_w[n];
        else if (col == 264) v = center_w[512 + n];
        else if (col == 265) v = b2[n] + conf_b[n] + center_b[n];
        else v = 0.0f;
        g_W2h[(size_t)n * KE + col] = __float2half(v);
    }

    for (int i = tid; i < 2560; i += 256) sW1[i] = W1[i];
    if (tid < 256){ sb1[tid] = b1[tid]; sg[tid] = lng[tid]; sbb[tid] = lnb[tid]; }
    for (int i = tid; i < 512; i += 256){ sdw[i] = dist_w[i]; sdb[i] = dist_b[i]; }
    __syncthreads();

    const float2* sW1f2 = (const float2*)sW1;
    const float2* sb1f2 = (const float2*)sb1;
    const float2* sgf2  = (const float2*)sg;
    const float2* sbbf2 = (const float2*)sbb;
    const float4* sdw4  = (const float4*)sdw;
    const float4* sdb4  = (const float4*)sdb;

    for (int it = 0; it < 2; it++){
        const int g = blockIdx.x * 16 + warp * 2 + it;
        const int cam = g % 3;

        const float4* bd4 = (const float4*)(box + (size_t)g * 12);
        float4 rA = __ldg(bd4), rB = __ldg(bd4+1), rC = __ldg(bd4+2);

        float c0[4], c1[4];
        c0[0]=rA.x/640.0f; c0[1]=rA.y/400.0f; c0[2]=rA.z/640.0f; c0[3]=rA.w/400.0f;
        c1[0]=rB.z/640.0f; c1[1]=rB.w/400.0f; c1[2]=rC.x/640.0f; c1[3]=rC.y/400.0f;
        float cat0=rB.x, conf0=rB.y, cat1=rC.z, conf1=rC.w;

        float s0 = ((c0[0]+c0[1])+c0[2])+c0[3];
        float s1 = ((c1[0]+c1[1])+c1[2])+c1[3];
        float p0 = (s0 != 0.0f) ? 1.0f : 0.0f;
        float p1 = (s1 != 0.0f) ? 1.0f : 0.0f;
        const bool swp = (cat1 + (1.0f-p1)*1000.0f) < (cat0 + (1.0f-p0)*1000.0f);

        float sc[2][4], scat[2], sconf[2], spres[2];
#pragma unroll
        for (int k = 0; k < 4; k++){
            sc[0][k] = swp ? c1[k] : c0[k];
            sc[1][k] = swp ? c0[k] : c1[k];
        }
        scat[0]=swp?cat1:cat0;   scat[1]=swp?cat0:cat1;
        sconf[0]=swp?conf1:conf0; sconf[1]=swp?conf0:conf1;
        spres[0]=swp?p1:p0;       spres[1]=swp?p0:p1;

        float feat[2][10], cxs[2], cys[2];
#pragma unroll
        for (int s = 0; s < 2; s++){
            float x1=sc[s][0], y1=sc[s][1], x2=sc[s][2], y2=sc[s][3];
            float w=x2-x1, h=y2-y1;
            float cx=(x1+x2)*0.5f, cy=(y1+y2)*0.5f;
            cxs[s]=cx; cys[s]=cy;
            feat[s][0]=x1; feat[s][1]=y1; feat[s][2]=x2; feat[s][3]=y2;
            feat[s][4]=w;  feat[s][5]=h;  feat[s][6]=cx; feat[s][7]=cy;
            feat[s][8]=w*h; feat[s][9]=w/(h+1e-6f);
        }

        float2 va[4], vb[4];
#pragma unroll
        for (int q = 0; q < 4; q++){
            int ci = lane + 32*q;
            float2 bias = sb1f2[ci];
            float2 a0 = bias, a1 = bias;
#pragma unroll
            for (int f = 0; f < 10; f++){
                float2 w2 = sW1f2[f*128 + ci];
                a0.x = fmaf(feat[0][f], w2.x, a0.x);
                a0.y = fmaf(feat[0][f], w2.y, a0.y);
                a1.x = fmaf(feat[1][f], w2.x, a1.x);
                a1.y = fmaf(feat[1][f], w2.y, a1.y);
            }
            va[q] = a0; vb[q] = a1;
        }

        float su0 = 0.f, su1 = 0.f;
#pragma unroll
        for (int q = 0; q < 4; q++){ su0 += va[q].x + va[q].y; su1 += vb[q].x + vb[q].y; }
#pragma unroll
        for (int o = 16; o; o >>= 1){
            su0 += __shfl_xor_sync(0xffffffffu, su0, o);
            su1 += __shfl_xor_sync(0xffffffffu, su1, o);
        }
        float mu0 = su0 * (1.0f/256.0f), mu1 = su1 * (1.0f/256.0f);

        float vr0 = 0.f, vr1 = 0.f;
#pragma unroll
        for (int q = 0; q < 4; q++){
            va[q].x -= mu0; va[q].y -= mu0;
            vb[q].x -= mu1; vb[q].y -= mu1;
            vr0 = fmaf(va[q].x, va[q].x, vr0); vr0 = fmaf(va[q].y, va[q].y, vr0);
            vr1 = fmaf(vb[q].x, vb[q].x, vr1); vr1 = fmaf(vb[q].y, vb[q].y, vr1);
        }
#pragma unroll
        for (int o = 16; o; o >>= 1){
            vr0 += __shfl_xor_sync(0xffffffffu, vr0, o);
            vr1 += __shfl_xor_sync(0xffffffffu, vr1, o);
        }
        float rs0 = rsqrtf(vr0 * (1.0f/256.0f) + 1e-5f);
        float rs1 = rsqrtf(vr1 * (1.0f/256.0f) + 1e-5f);

        __half2* hrow0 = (__half2*)(g_Hh + (size_t)(2*g + 0)*KE);
        __half2* hrow1 = (__half2*)(g_Hh + (size_t)(2*g + 1)*KE);
#pragma unroll
        for (int q = 0; q < 4; q++){
            int ci = lane + 32*q;
            float2 gb = sgf2[ci], bv = sbbf2[ci];
            float y00 = gelu_fast(va[q].x * rs0 * gb.x + bv.x);
            float y01 = gelu_fast(va[q].y * rs0 * gb.y + bv.y);
            float y10 = gelu_fast(vb[q].x * rs1 * gb.x + bv.x);
            float y11 = gelu_fast(vb[q].y * rs1 * gb.y + bv.y);
            hrow0[ci] = __floats2half2_rn(y00, y01);
            hrow1[ci] = __floats2half2_rn(y10, y11);
        }
        // extension columns 256..287 (16 half2 per row)
        if (lane < 16){
            int col = 256 + 2*lane;
            hrow0[128 + lane] = __floats2half2_rn(
                ext_val(col,   scat[0], sconf[0], cxs[0], cys[0], cam),
                ext_val(col+1, scat[0], sconf[0], cxs[0], cys[0], cam));
            hrow1[128 + lane] = __floats2half2_rn(
                ext_val(col,   scat[1], sconf[1], cxs[1], cys[1], cam),
                ext_val(col+1, scat[1], sconf[1], cxs[1], cys[1], cam));
        }

        float dx = cxs[0]-cxs[1], dy = cys[0]-cys[1];
        float dist = sqrtf(dx*dx + dy*dy);
        const int bI = g / (NB_T*NB_NC);
        const int rem = g % (NB_T*NB_NC);
        float4* orow4 = (float4*)(out + ((size_t)bI * 1800 + rem) * 512);
#pragma unroll
        for (int jj = 0; jj < 4; jj++){
            int ci = lane + 32*jj;
            float4 w4 = sdw4[ci], b4 = sdb4[ci];
            float4 r4;
            r4.x = fmaf(dist, w4.x, b4.x);
            r4.y = fmaf(dist, w4.y, b4.y);
            r4.z = fmaf(dist, w4.z, b4.z);
            r4.w = fmaf(dist, w4.w, b4.w);
            orow4[ci] = r4;
        }
        if (lane < 2){
            g_pres[2*g + lane] = spres[lane];
        }
    }
}

// ---------------------------------------------------------------------------
// k_gemm: warp-specialized fp16 GEMM over extended K=288 (9 chunks of 32).
// CTA tile 128x128, 8 consumer warps (64x32) + 1 producer. 4-stage mbarrier
// ring, producer keeps 3 chunk-loads in flight (wait_group 2). 2 CTAs/SM.
// ---------------------------------------------------------------------------
#define RST 40                              /* stage row stride in halves */
#define STG_BYTES (256*RST*2)               /* 20480 B */
#define NSTG 4
#define NKC  9                              /* 288/32 */

__global__ __launch_bounds__(288, 2) void k_gemm(
    const float* __restrict__ missing,
    const float* __restrict__ scalep,
    float* __restrict__ out)
{
    extern __shared__ __align__(16) char smraw[];   // 4 stages x 20480 B
    __shared__ __align__(8) uint64_t s_bar[2*NSTG]; // full[0..3], empty[4..7]
    __shared__ float s_pres[128];

    const int tid  = threadIdx.x;
    const int lane = tid & 31;
    const int warp = tid >> 5;

    const int n0 = blockIdx.x * 128;
    const int m0 = blockIdx.y * 128;

    if (tid == 0){
#pragma unroll
        for (int s = 0; s < NSTG; s++){
            MBAR_INIT(smem_u32(&s_bar[s]), 1);          // full: producer arrives
            MBAR_INIT(smem_u32(&s_bar[NSTG+s]), 8);     // empty: 8 consumer warps
        }
    }
    if (tid < 128) s_pres[tid] = g_pres[m0 + tid];
    __syncthreads();

    const uint32_t base = smem_u32(smraw);

    if (warp == 8){
        // ================= producer (depth-3 in-flight) =================
        int eph = 1, es = 0;       // empty-wait cursor (phase starts 1)
        int fp  = 0;               // full-arrive cursor (lags issue by 2)
#pragma unroll 1
        for (int kc = 0; kc < NKC; kc++){
            mbar_wait(smem_u32(&s_bar[NSTG + es]), eph);
            if (++es == NSTG){ es = 0; eph ^= 1; }
            uint32_t stg = base + (kc & 3) * STG_BYTES;
            const int ko = kc * 32;
#pragma unroll
            for (int u = 0; u < 16; u++){               // A: 512 chunks
                int c = lane + u*32;
                int row = c >> 2, seg = c & 3;
                const __half* src = g_Hh + (size_t)(m0 + row) * KE + ko + seg*8;
                CP16(stg + row*80 + seg*16, src);
            }
#pragma unroll
            for (int u = 0; u < 16; u++){               // B: 512 chunks
                int c = lane + u*32;
                int n = c >> 2, seg = c & 3;
                const __half* src = g_W2h + (size_t)(n0 + n) * KE + ko + seg*8;
                CP16(stg + (128 + n)*80 + seg*16, src);
            }
            CPCOMMIT();
            if (kc >= 2){
                CPWAIT2();
                if (lane == 0) MBAR_ARRIVE(smem_u32(&s_bar[fp]));
                fp = (fp + 1) & 3;
            }
        }
        CPWAIT1();
        if (lane == 0) MBAR_ARRIVE(smem_u32(&s_bar[fp]));
        fp = (fp + 1) & 3;
        CPWAIT0();
        if (lane == 0) MBAR_ARRIVE(smem_u32(&s_bar[fp]));
    } else {
        // ================= consumers =================
        const int wm  = warp & 1;      // 2 warps along M (64 rows each)
        const int wn  = warp >> 1;     // 4 warps along N (32 cols each)
        const int gid = lane >> 2;
        const int tig = lane & 3;

        const int a_row_sel = (lane & 7) + ((lane >> 3) & 1) * 8;
        const int a_col_sel = ((lane >> 4) & 1) * 8;
        const int b_row_sel = (lane & 7) + ((lane >> 4) & 1) * 8;
        const int b_col_sel = ((lane >> 3) & 1) * 8;

        // preload missing values for this thread's 8 output columns
        float2 ms[4];
#pragma unroll
        for (int ni = 0; ni < 4; ni++){
            int dl = wn*32 + ni*8 + tig*2;
            ms[ni] = *reinterpret_cast<const float2*>(missing + n0 + dl);
        }
        const float scaleV = *scalep;

        float acc[4][4][4];
#pragma unroll
        for (int i = 0; i < 4; i++)
#pragma unroll
            for (int j = 0; j < 4; j++)
#pragma unroll
                for (int k = 0; k < 4; k++) acc[i][j][k] = 0.0f;

        int fph = 0, fs = 0;
#pragma unroll 1
        for (int kc = 0; kc < NKC; kc++){
            mbar_wait(smem_u32(&s_bar[fs]), fph);
            const uint32_t s32 = base + (kc & 3) * STG_BYTES;
#pragma unroll
            for (int ks = 0; ks < 2; ks++){
                const int kk = ks * 16;
                uint32_t af[4][4];
#pragma unroll
                for (int mi = 0; mi < 4; mi++){
                    int row = wm*64 + mi*16 + a_row_sel;
                    ldsm_x4(af[mi], s32 + (row*RST + kk + a_col_sel)*2);
                }
                uint32_t bf[4][2];
#pragma unroll
                for (int nio = 0; nio < 2; nio++){
                    uint32_t r[4];
                    int nrow = 128 + wn*32 + nio*16 + b_row_sel;
                    ldsm_x4(r, s32 + (nrow*RST + kk + b_col_sel)*2);
                    bf[nio*2  ][0] = r[0]; bf[nio*2  ][1] = r[1];
                    bf[nio*2+1][0] = r[2]; bf[nio*2+1][1] = r[3];
                }
#pragma unroll
                for (int mi = 0; mi < 4; mi++)
#pragma unroll
                    for (int ni = 0; ni < 4; ni++)
                        mma_f16(acc[mi][ni], af[mi], bf[ni]);
            }
            if (lane == 0) MBAR_ARRIVE(smem_u32(&s_bar[NSTG + fs]));
            if (++fs == NSTG){ fs = 0; fph ^= 1; }
        }

        // ---- epilogue: scale + presence mask ----
#pragma unroll
        for (int mi = 0; mi < 4; mi++){
#pragma unroll
            for (int h = 0; h < 2; h++){
                int lm = wm*64 + mi*16 + gid + h*8;
                int m  = m0 + lm;
                float pres = s_pres[lm];
                int bI  = m / 1200;
                int rem = m % 1200;
                float* orow = out + ((size_t)bI*1800 + 600 + rem) * 512 + n0;
#pragma unroll
                for (int ni = 0; ni < 4; ni++){
                    int dl = wn*32 + ni*8 + tig*2;
                    float v0 = acc[mi][ni][h*2 + 0] * scaleV;
                    float v1 = acc[mi][ni][h*2 + 1] * scaleV;
                    if (pres == 0.0f){ v0 = ms[ni].x; v1 = ms[ni].y; }
                    float2 w2; w2.x = v0; w2.y = v1;
                    *reinterpret_cast<float2*>(orow + dl) = w2;
                }
            }
        }
    }
}

// ---------------------------------------------------------------------------
extern "C" void kernel_launch(void* const* d_in, const int* in_sizes, int n_in,
                              void* d_out, int out_size)
{
    const float* box        = (const float*)d_in[0];
    const float* cat_table  = (const float*)d_in[1];
    const float* W1         = (const float*)d_in[2];
    const float* b1         = (const float*)d_in[3];
    const float* lng        = (const float*)d_in[4];
    const float* lnb        = (const float*)d_in[5];
    const float* W2         = (const float*)d_in[6];
    const float* b2         = (const float*)d_in[7];
    const float* conf_w     = (const float*)d_in[8];
    const float* conf_b     = (const float*)d_in[9];
    const float* center_w   = (const float*)d_in[10];
    const float* center_b   = (const float*)d_in[11];
    const float* missing    = (const float*)d_in[12];
    const float* dist_w     = (const float*)d_in[13];
    const float* dist_b     = (const float*)d_in[14];
    const float* cam_table  = (const float*)d_in[15];
    const float* scalep     = (const float*)d_in[16];
    float* out = (float*)d_out;

    const int dyn_smem = NSTG * STG_BYTES;   // 81920 B
    cudaFuncSetAttribute(k_gemm, cudaFuncAttributeMaxDynamicSharedMemorySize, dyn_smem);

    k_features<<<4800, 256>>>(box, W1, b1, lng, lnb, dist_w, dist_b, W2,
                              b2, conf_w, conf_b, center_w, center_b,
                              cat_table, cam_table, out);
    k_gemm<<<dim3(4, 1200), 288, dyn_smem>>>(missing, scalep, out);
}